// round 4
// baseline (speedup 1.0000x reference)
#include <cuda_runtime.h>
#include <cuda_fp16.h>
#include <math.h>

#define VOL (128*128*128)
#define NB 8

typedef unsigned long long u64;

// Packed spectra FFT(o + i*t): [vol][kx][z][y], fp16 complex => 67MB
__device__ __half2 g_ft[(size_t)NB * VOL];
// Accumulators: c3*520 + shell*8 + bc
__device__ float g_acc[3 * 65 * NB];
__device__ unsigned g_done;

// packed-f32x2 constants
#define ONE2 0x3F8000003F800000ull   // ( 1,  1)
#define NEG2 0xBF800000BF800000ull   // (-1, -1)
#define PMI2 0xBF8000003F800000ull   // (+1, -1)  lo=+1, hi=-1
#define SC2K 0x3DB504F33DB504F3ull   // (1/sqrt(128)) x2

__device__ __forceinline__ u64 pack2(float x, float y) {
    u64 r; asm("mov.b64 %0,{%1,%2};" : "=l"(r) : "f"(x), "f"(y)); return r;
}
__device__ __forceinline__ float2 unpack2(u64 v) {
    float2 r; asm("mov.b64 {%0,%1},%2;" : "=f"(r.x), "=f"(r.y) : "l"(v)); return r;
}
__device__ __forceinline__ u64 swap2(u64 v) {
    float2 t = unpack2(v); return pack2(t.y, t.x);
}
__device__ __forceinline__ u64 fma2(u64 a, u64 b, u64 c) {
    u64 r; asm("fma.rn.f32x2 %0,%1,%2,%3;" : "=l"(r) : "l"(a), "l"(b), "l"(c)); return r;
}
__device__ __forceinline__ u64 mul2(u64 a, u64 b) {
    u64 r; asm("mul.rn.f32x2 %0,%1,%2;" : "=l"(r) : "l"(a), "l"(b)); return r;
}
__device__ __forceinline__ u64 add2(u64 a, u64 b) {
    u64 r; asm("add.rn.f32x2 %0,%1,%2;" : "=l"(r) : "l"(a), "l"(b)); return r;
}
__device__ __forceinline__ u64 h2p(__half2 h) {
    float2 f = __half22float2(h); return pack2(f.x, f.y);
}
__device__ __forceinline__ __half2 p2h(u64 v) {
    float2 f = unpack2(v); return __float22half2_rn(f);
}
__device__ __forceinline__ int rev5(int i) { return (int)(__brev((unsigned)i) >> 27); }

// ---------------------------------------------------------------------------
// 128-pt forward FFT, one warp, 4 packed complex (lo=re, hi=im) per lane.
// Output natural index i = 4*lane + r. Input bit-reversed:
// v[r] = src[rev5(lane) + {0,64,32,96}[r]]. twq[k] = (cos,cos,-sin,sin), k<64.
__device__ __forceinline__ void warp_fft128p(u64 v[4], int lane, const float4* twq) {
    const u64 neg = NEG2, pmi = PMI2;
    u64 a, b;
    // len=2
    a = v[0]; b = v[1]; v[0] = add2(a, b); v[1] = fma2(b, neg, a);
    a = v[2]; b = v[3]; v[2] = add2(a, b); v[3] = fma2(b, neg, a);
    // len=4 : (0,2) w=1 ; (1,3) w=-i
    a = v[0]; b = v[2]; v[0] = add2(a, b); v[2] = fma2(b, neg, a);
    a = v[1]; b = mul2(swap2(v[3]), pmi);          // -i * v3
    v[1] = add2(a, b); v[3] = fma2(b, neg, a);
    // 5 shuffle stages
#pragma unroll
    for (int s = 0; s < 5; s++) {
        int m = 1 << s;
        bool hi = (lane & m) != 0;
        u64 sgn2 = hi ? NEG2 : ONE2;
#pragma unroll
        for (int r = 0; r < 4; r++) {
            int idx = ((((lane & (m - 1)) << 2) | r) << (4 - s));
            float4 q = twq[idx];
            u64 wc = pack2(q.x, q.y);              // ( c,  c)
            u64 ws = pack2(q.z, q.w);              // (-s,  s)
            u64 oth = __shfl_xor_sync(0xffffffffu, v[r], m);
            u64 uu = hi ? oth : v[r];
            u64 bb = hi ? v[r] : oth;
            u64 wv = fma2(ws, swap2(bb), mul2(wc, bb));
            v[r] = fma2(sgn2, wv, uu);
        }
    }
}

__device__ __forceinline__ void init_twq(float4* twq, int tid) {
    if (tid < 64) {
        float sv, cv;
        sincosf(-6.283185307179586f * (float)tid * (1.0f / 128.0f), &sv, &cv);
        twq[tid] = make_float4(cv, cv, -sv, sv);
    }
}

// ---------------------------------------------------------------------------
// Pass 1: pack P = o + i*t, x-FFT, fp16 transposed out to [vol][kx][z][y].
__global__ void __launch_bounds__(1024) k_fft_x(const float* __restrict__ a_in,
                                                const float* __restrict__ b_in) {
    __shared__ float4 twq[64];
    __shared__ __half2 tile[32][129];
    int tid = threadIdx.x, lane = tid & 31, w = tid >> 5;
    init_twq(twq, tid);

    unsigned b = blockIdx.x;              // 8 vols * 128 z * 4 ytiles = 4096
    unsigned ytile = b & 3u;
    unsigned z     = (b >> 2) & 127u;
    unsigned vol   = b >> 9;

    size_t off = (size_t)vol * VOL + (size_t)z * 16384 + (size_t)(ytile * 32 + w) * 128;
    const float* so = a_in + off;
    const float* st = b_in + off;
    __syncthreads();                      // twq ready

    int rb = rev5(lane);
    u64 v[4];
    v[0] = pack2(so[rb],      st[rb]);
    v[1] = pack2(so[rb + 64], st[rb + 64]);
    v[2] = pack2(so[rb + 32], st[rb + 32]);
    v[3] = pack2(so[rb + 96], st[rb + 96]);
    warp_fft128p(v, lane, twq);

    const u64 sc2 = SC2K;
#pragma unroll
    for (int r = 0; r < 4; r++)
        tile[w][4 * lane + r] = p2h(mul2(v[r], sc2));
    __syncthreads();

    size_t base = (size_t)vol * VOL + (size_t)z * 128 + ytile * 32 + lane;
#pragma unroll
    for (int xi = 0; xi < 4; xi++) {
        int kx = w * 4 + xi;
        g_ft[base + (size_t)kx * 16384] = tile[lane][kx];
    }
}

// ---------------------------------------------------------------------------
// Pass 2: per (bc, kx-pair): load plane(s), y-FFT in smem, z-FFT in registers
// (column + mirror column per warp), shuffle-based Hermitian pairing, reduce.
#define SMEM2 (64 * 16 + 2 * 128 * 129 * 4 + 32 * 196 * 4)

__global__ void __launch_bounds__(1024, 1) k_fft_yz_reduce(float* __restrict__ out) {
    extern __shared__ unsigned char smem_raw[];
    float4*  twq  = (float4*)smem_raw;                    // 1KB
    __half2* pA   = (__half2*)(smem_raw + 1024);          // [z][y] pitch 129
    __half2* pBs  = pA + 128 * 129;
    float*   bins = (float*)(pBs + 128 * 129);            // [warp][196]
    __shared__ bool s_last;
    __shared__ float red[NB];

    int tid = threadIdx.x, lane = tid & 31, w = tid >> 5;
    init_twq(twq, tid);
    for (int i = tid; i < 32 * 196; i += 1024) bins[i] = 0.0f;

    unsigned bc  = blockIdx.x / 65;
    unsigned kx1 = blockIdx.x % 65;
    unsigned kx2 = (128u - kx1) & 127u;
    bool dual = (kx2 != kx1);
    __half2* pB = dual ? pBs : pA;

    const __half2* gA = g_ft + ((size_t)bc * 128 + kx1) * 16384;
    const __half2* gB = g_ft + ((size_t)bc * 128 + kx2) * 16384;
#pragma unroll
    for (int i = 0; i < 16; i++) {
        int idx = tid + i * 1024;
        int z = idx >> 7, y = idx & 127;
        pA[z * 129 + y] = gA[idx];
        if (dual) pBs[z * 129 + y] = gB[idx];
    }
    __syncthreads();

    int rb = rev5(lane);
    const u64 sc2 = SC2K;
    int npl = dual ? 2 : 1;

    // y-FFT in place: 128 rows per plane, 4 per warp
    for (int p = 0; p < npl; p++) {
        __half2* pl = p ? pBs : pA;
#pragma unroll
        for (int i = 0; i < 4; i++) {
            __half2* rowp = pl + (w + 32 * i) * 129;
            u64 v[4];
            v[0] = h2p(rowp[rb]);
            v[1] = h2p(rowp[rb + 64]);
            v[2] = h2p(rowp[rb + 32]);
            v[3] = h2p(rowp[rb + 96]);
            warp_fft128p(v, lane, twq);
#pragma unroll
            for (int r = 0; r < 4; r++)
                rowp[4 * lane + r] = p2h(mul2(v[r], sc2));
        }
    }
    __syncthreads();

    // z-FFT in registers + shuffle-paired Hermitian split + shell reduce.
    // Warp handles column yA of plane A and mirror column yB of plane B.
    // z-norm (1/128 total for the product) folded into cfac.
    int fx = (int)kx1; if (fx >= 64) fx -= 128;
    float cfac = dual ? (0.5f / 128.0f) : (0.25f / 128.0f);
    float* mybins = bins + w * 196;

#pragma unroll
    for (int i = 0; i < 4; i++) {
        int yA = w + 32 * i;
        int yB = (128 - yA) & 127;
        u64 va[4], vb[4];
        va[0] = h2p(pA[ rb       * 129 + yA]);
        va[1] = h2p(pA[(rb + 64) * 129 + yA]);
        va[2] = h2p(pA[(rb + 32) * 129 + yA]);
        va[3] = h2p(pA[(rb + 96) * 129 + yA]);
        warp_fft128p(va, lane, twq);
        vb[0] = h2p(pB[ rb       * 129 + yB]);
        vb[1] = h2p(pB[(rb + 64) * 129 + yB]);
        vb[2] = h2p(pB[(rb + 32) * 129 + yB]);
        vb[3] = h2p(pB[(rb + 96) * 129 + yB]);
        warp_fft128p(vb, lane, twq);

        // pair F(k) (va, slot kz=4*lane+r) with F(-k) (vb col, index (128-kz)&127)
        float2 B0 = unpack2(vb[0]), B1 = unpack2(vb[1]);
        float2 B2 = unpack2(vb[2]), B3 = unpack2(vb[3]);
        int l0 = (32 - lane) & 31, l1 = 31 - lane;
        float2 Fm[4];
        Fm[0].x = __shfl_sync(0xffffffffu, B0.x, l0);
        Fm[0].y = __shfl_sync(0xffffffffu, B0.y, l0);
        Fm[1].x = __shfl_sync(0xffffffffu, B3.x, l1);
        Fm[1].y = __shfl_sync(0xffffffffu, B3.y, l1);
        Fm[2].x = __shfl_sync(0xffffffffu, B2.x, l1);
        Fm[2].y = __shfl_sync(0xffffffffu, B2.y, l1);
        Fm[3].x = __shfl_sync(0xffffffffu, B1.x, l1);
        Fm[3].y = __shfl_sync(0xffffffffu, B1.y, l1);

        int fy = (yA >= 64) ? yA - 128 : yA;
        int fxy2 = fx * fx + fy * fy;
#pragma unroll
        for (int r = 0; r < 4; r++) {
            int kz = 4 * lane + r;
            int fz = (kz >= 64) ? kz - 128 : kz;
            int r2 = fz * fz + fxy2;
            int sh = (int)sqrtf((float)r2);          // exact truncation
            if (sh <= 64) {
                float2 F = unpack2(va[r]);
                float Ox = F.x + Fm[r].x, Oy = F.y - Fm[r].y;   // 2*O
                float Tx = F.y + Fm[r].y, Ty = Fm[r].x - F.x;   // 2*T
                atomicAdd(&mybins[sh * 3 + 0], cfac * (Ox * Tx + Oy * Ty));
                atomicAdd(&mybins[sh * 3 + 1], cfac * (Ox * Ox + Oy * Oy));
                atomicAdd(&mybins[sh * 3 + 2], cfac * (Tx * Tx + Ty * Ty));
            }
        }
    }
    __syncthreads();

    // fold per-warp bins -> global accumulators
    if (tid < 195) {
        float s = 0.0f;
#pragma unroll
        for (int ww = 0; ww < 32; ww++) s += bins[ww * 196 + tid];
        int sh = tid / 3, c3 = tid % 3;
        atomicAdd(&g_acc[c3 * 520 + sh * 8 + bc], s);
    }
    __syncthreads();

    // last block computes the loss and resets global state (graph-replay safe)
    if (tid == 0) {
        __threadfence();
        unsigned old = atomicAdd(&g_done, 1u);
        s_last = (old == gridDim.x - 1);
    }
    __syncthreads();
    if (!s_last) return;

    float* sacc = bins;
    for (int i = tid; i < 3 * 65 * NB; i += 1024)
        sacc[i] = atomicExch(&g_acc[i], 0.0f);
    __syncthreads();

    if (tid < NB) {
        float acc = 0.0f;
        for (int s = 1; s <= 64; s++) {
            float n  = sacc[0 * 520 + s * 8 + tid];
            float po = sacc[1 * 520 + s * 8 + tid];
            float pt = sacc[2 * 520 + s * 8 + tid];
            float f = n / sqrtf(po * pt + 1e-6f);
            acc += fminf(1.0f, fmaxf(-1.0f, f));
        }
        red[tid] = 1.0f - acc * (1.0f / 64.0f);
    }
    __syncthreads();
    if (tid == 0) {
        float m = 0.0f;
#pragma unroll
        for (int i = 0; i < NB; i++) m += red[i];
        out[0] = m * (1.0f / (float)NB);
        atomicExch(&g_done, 0u);
    }
}

// ---------------------------------------------------------------------------
extern "C" void kernel_launch(void* const* d_in, const int* in_sizes, int n_in,
                              void* d_out, int out_size) {
    const float* model_output = (const float*)d_in[0];
    const float* target       = (const float*)d_in[1];

    cudaFuncSetAttribute(k_fft_yz_reduce,
                         cudaFuncAttributeMaxDynamicSharedMemorySize, SMEM2);

    k_fft_x<<<8 * 128 * 4, 1024>>>(model_output, target);
    k_fft_yz_reduce<<<8 * 65, 1024, SMEM2>>>((float*)d_out);
}

// round 5
// speedup vs baseline: 2.9337x; 2.9337x over previous
#include <cuda_runtime.h>
#include <cuda_fp16.h>
#include <math.h>

#define VOL (128*128*128)          // 2^21
#define NB 8                        // batch*channels

// Packed spectra FFT(o + i*t): [vol][kx][z][y], fp16 complex => 67MB
__device__ __half2 g_ft[(size_t)NB * VOL];
// Accumulators: c3*520 + shell*8 + bc ; c3: 0=num, 1=out power, 2=tgt power
__device__ float g_acc[3 * 65 * NB];
__device__ unsigned g_done;        // zero-initialized; restored to 0 each launch

__device__ __forceinline__ float2 cmul(float2 a, float2 b) {
    return make_float2(fmaf(a.x, b.x, -a.y * b.y), fmaf(a.x, b.y, a.y * b.x));
}
__device__ __forceinline__ int rev5(int i) { return (int)(__brev((unsigned)i) >> 27); }

// ---------------------------------------------------------------------------
// 128-point forward FFT within one warp; 4 complex values per lane.
// Output (natural) index i = 4*lane + r. Input loaded bit-reversed:
// v[r] = src[rev5(lane) + {0,64,32,96}[r]].  tw[k]=exp(-2*pi*i*k/128), k<64.
__device__ __forceinline__ void warp_fft128(float2 v[4], int lane, const float2* tw) {
    float2 t;
    // len=2
    t = v[1]; v[1] = make_float2(v[0].x - t.x, v[0].y - t.y);
              v[0] = make_float2(v[0].x + t.x, v[0].y + t.y);
    t = v[3]; v[3] = make_float2(v[2].x - t.x, v[2].y - t.y);
              v[2] = make_float2(v[2].x + t.x, v[2].y + t.y);
    // len=4 : (0,2) w=1 ; (1,3) w=-i
    t = v[2]; v[2] = make_float2(v[0].x - t.x, v[0].y - t.y);
              v[0] = make_float2(v[0].x + t.x, v[0].y + t.y);
    t = make_float2(v[3].y, -v[3].x);
    v[3] = make_float2(v[1].x - t.x, v[1].y - t.y);
    v[1] = make_float2(v[1].x + t.x, v[1].y + t.y);
    // 5 shuffle stages
#pragma unroll
    for (int s = 0; s < 5; s++) {
        int m = 1 << s;
        bool hi = (lane & m) != 0;
        float sgn = hi ? -1.0f : 1.0f;
#pragma unroll
        for (int r = 0; r < 4; r++) {
            int pos = ((lane & (m - 1)) << 2) | r;
            float2 w = tw[pos << (4 - s)];
            float2 mine = v[r];
            float2 oth;
            oth.x = __shfl_xor_sync(0xffffffffu, mine.x, m);
            oth.y = __shfl_xor_sync(0xffffffffu, mine.y, m);
            float2 u  = hi ? oth : mine;
            float2 vv = hi ? mine : oth;
            float2 wv = cmul(w, vv);
            v[r] = make_float2(fmaf(sgn, wv.x, u.x), fmaf(sgn, wv.y, u.y));
        }
    }
}

__device__ __forceinline__ void init_tw(float2* tw, int tid) {
    if (tid < 64) {
        float sv, cv;
        sincosf(-6.283185307179586f * (float)tid * (1.0f / 128.0f), &sv, &cv);
        tw[tid] = make_float2(cv, sv);
    }
}

// ---------------------------------------------------------------------------
// Pass 1: pack P = o + i*t, x-FFT, write fp16 transposed to [vol][kx][z][y].
__global__ void __launch_bounds__(1024) k_fft_x(const float* __restrict__ a_in,
                                                const float* __restrict__ b_in) {
    __shared__ float2 tw[64];
    __shared__ __half2 tile[32][129];
    int tid = threadIdx.x, lane = tid & 31, w = tid >> 5;
    init_tw(tw, tid);

    unsigned b = blockIdx.x;              // 8 vols * 128 z * 4 ytiles = 4096
    unsigned ytile = b & 3u;
    unsigned z     = (b >> 2) & 127u;
    unsigned vol   = b >> 9;

    size_t off = (size_t)vol * VOL + (size_t)z * 16384 + (size_t)(ytile * 32 + w) * 128;
    const float* so = a_in + off;
    const float* st = b_in + off;
    __syncthreads();                      // tw ready

    int rb = rev5(lane);
    float2 v[4];
    v[0] = make_float2(so[rb],      st[rb]);
    v[1] = make_float2(so[rb + 64], st[rb + 64]);
    v[2] = make_float2(so[rb + 32], st[rb + 32]);
    v[3] = make_float2(so[rb + 96], st[rb + 96]);
    warp_fft128(v, lane, tw);

    const float sc = 0.08838834764831845f;    // 1/sqrt(128)
#pragma unroll
    for (int r = 0; r < 4; r++)
        tile[w][4 * lane + r] = __float22half2_rn(make_float2(v[r].x * sc, v[r].y * sc));
    __syncthreads();

    size_t base = (size_t)vol * VOL + (size_t)z * 128 + ytile * 32 + lane;
#pragma unroll
    for (int xi = 0; xi < 4; xi++) {
        int kx = w * 4 + xi;
        g_ft[base + (size_t)kx * 16384] = tile[lane][kx];
    }
}

// ---------------------------------------------------------------------------
// Pass 2: per (bc, kx-pair): load plane(s), y-FFT in smem, z-FFT in REGISTERS
// (column of A + mirror column of B per warp), shuffle Hermitian pairing,
// shell-reduce. Last block computes the loss and resets global state.
#define SMEM2 (64 * 8 + 2 * 128 * 129 * 4 + 32 * 196 * 4)

__global__ void __launch_bounds__(1024, 1) k_fft_yz_reduce(float* __restrict__ out) {
    extern __shared__ unsigned char smem_raw[];
    float2*  tw   = (float2*)smem_raw;                    // 512B
    __half2* pA   = (__half2*)(smem_raw + 512);           // [z][y] pitch 129
    __half2* pBs  = pA + 128 * 129;
    float*   bins = (float*)(pBs + 128 * 129);            // [warp][196]
    __shared__ bool s_last;
    __shared__ float red[NB];

    int tid = threadIdx.x, lane = tid & 31, w = tid >> 5;
    init_tw(tw, tid);
    for (int i = tid; i < 32 * 196; i += 1024) bins[i] = 0.0f;

    unsigned bc  = blockIdx.x / 65;
    unsigned kx1 = blockIdx.x % 65;
    unsigned kx2 = (128u - kx1) & 127u;
    bool dual = (kx2 != kx1);
    __half2* pB = dual ? pBs : pA;

    const __half2* gA = g_ft + ((size_t)bc * 128 + kx1) * 16384;
    const __half2* gB = g_ft + ((size_t)bc * 128 + kx2) * 16384;
#pragma unroll
    for (int i = 0; i < 16; i++) {
        int idx = tid + i * 1024;
        int z = idx >> 7, y = idx & 127;
        pA[z * 129 + y] = gA[idx];
        if (dual) pBs[z * 129 + y] = gB[idx];
    }
    __syncthreads();

    int rb = rev5(lane);
    const float sc = 0.08838834764831845f;
    int npl = dual ? 2 : 1;

    // y-FFT in place: 128 rows per plane, 4 per warp
    for (int p = 0; p < npl; p++) {
        __half2* pl = p ? pBs : pA;
#pragma unroll
        for (int i = 0; i < 4; i++) {
            __half2* rowp = pl + (w + 32 * i) * 129;
            float2 v[4];
            v[0] = __half22float2(rowp[rb]);
            v[1] = __half22float2(rowp[rb + 64]);
            v[2] = __half22float2(rowp[rb + 32]);
            v[3] = __half22float2(rowp[rb + 96]);
            warp_fft128(v, lane, tw);
#pragma unroll
            for (int r = 0; r < 4; r++)
                rowp[4 * lane + r] = __float22half2_rn(make_float2(v[r].x * sc, v[r].y * sc));
        }
    }
    __syncthreads();

    // z-FFT in registers + shuffle-paired Hermitian split + shell reduce.
    // Warp handles column yA of plane A and mirror column yB of plane B.
    // z-norm (1/128 on products) folded into cfac.
    int fx = (int)kx1; if (fx >= 64) fx -= 128;
    float cfac = dual ? (0.5f / 128.0f) : (0.25f / 128.0f);
    float* mybins = bins + w * 196;

#pragma unroll
    for (int i = 0; i < 4; i++) {
        int yA = w + 32 * i;
        int yB = (128 - yA) & 127;

        // mirror column first: FFT, then shuffle-gather F(-k); vb dies early
        float2 Fm[4];
        {
            float2 vb[4];
            vb[0] = __half22float2(pB[ rb       * 129 + yB]);
            vb[1] = __half22float2(pB[(rb + 64) * 129 + yB]);
            vb[2] = __half22float2(pB[(rb + 32) * 129 + yB]);
            vb[3] = __half22float2(pB[(rb + 96) * 129 + yB]);
            warp_fft128(vb, lane, tw);
            // pair slot kz=4*lane+r with index (128-kz)&127 of this column
            int l0 = (32 - lane) & 31, l1 = 31 - lane;
            Fm[0].x = __shfl_sync(0xffffffffu, vb[0].x, l0);
            Fm[0].y = __shfl_sync(0xffffffffu, vb[0].y, l0);
            Fm[1].x = __shfl_sync(0xffffffffu, vb[3].x, l1);
            Fm[1].y = __shfl_sync(0xffffffffu, vb[3].y, l1);
            Fm[2].x = __shfl_sync(0xffffffffu, vb[2].x, l1);
            Fm[2].y = __shfl_sync(0xffffffffu, vb[2].y, l1);
            Fm[3].x = __shfl_sync(0xffffffffu, vb[1].x, l1);
            Fm[3].y = __shfl_sync(0xffffffffu, vb[1].y, l1);
        }

        float2 va[4];
        va[0] = __half22float2(pA[ rb       * 129 + yA]);
        va[1] = __half22float2(pA[(rb + 64) * 129 + yA]);
        va[2] = __half22float2(pA[(rb + 32) * 129 + yA]);
        va[3] = __half22float2(pA[(rb + 96) * 129 + yA]);
        warp_fft128(va, lane, tw);

        int fy = (yA >= 64) ? yA - 128 : yA;
        int fxy2 = fx * fx + fy * fy;
#pragma unroll
        for (int r = 0; r < 4; r++) {
            int kz = 4 * lane + r;
            int fz = (kz >= 64) ? kz - 128 : kz;
            int r2 = fz * fz + fxy2;
            int sh = (int)sqrtf((float)r2);          // exact truncation
            if (sh <= 64) {
                float2 F = va[r];
                float Ox = F.x + Fm[r].x, Oy = F.y - Fm[r].y;   // 2*O
                float Tx = F.y + Fm[r].y, Ty = Fm[r].x - F.x;   // 2*T
                atomicAdd(&mybins[sh * 3 + 0], cfac * (Ox * Tx + Oy * Ty));
                atomicAdd(&mybins[sh * 3 + 1], cfac * (Ox * Ox + Oy * Oy));
                atomicAdd(&mybins[sh * 3 + 2], cfac * (Tx * Tx + Ty * Ty));
            }
        }
    }
    __syncthreads();

    // fold per-warp bins -> global accumulators
    if (tid < 195) {
        float s = 0.0f;
#pragma unroll
        for (int ww = 0; ww < 32; ww++) s += bins[ww * 196 + tid];
        int sh = tid / 3, c3 = tid % 3;
        atomicAdd(&g_acc[c3 * 520 + sh * 8 + bc], s);
    }
    __syncthreads();

    // completion counter; last block computes the loss and resets state
    if (tid == 0) {
        __threadfence();
        unsigned old = atomicAdd(&g_done, 1u);
        s_last = (old == gridDim.x - 1);
    }
    __syncthreads();
    if (!s_last) return;

    float* sacc = bins;   // reuse smem
    for (int i = tid; i < 3 * 65 * NB; i += 1024)
        sacc[i] = atomicExch(&g_acc[i], 0.0f);    // read + reset for next replay
    __syncthreads();

    if (tid < NB) {
        float acc = 0.0f;
        for (int s = 1; s <= 64; s++) {
            float n  = sacc[0 * 520 + s * 8 + tid];
            float po = sacc[1 * 520 + s * 8 + tid];
            float pt = sacc[2 * 520 + s * 8 + tid];
            float f = n / sqrtf(po * pt + 1e-6f);
            acc += fminf(1.0f, fmaxf(-1.0f, f));
        }
        red[tid] = 1.0f - acc * (1.0f / 64.0f);
    }
    __syncthreads();
    if (tid == 0) {
        float m = 0.0f;
#pragma unroll
        for (int i = 0; i < NB; i++) m += red[i];
        out[0] = m * (1.0f / (float)NB);
        atomicExch(&g_done, 0u);
    }
}

// ---------------------------------------------------------------------------
extern "C" void kernel_launch(void* const* d_in, const int* in_sizes, int n_in,
                              void* d_out, int out_size) {
    const float* model_output = (const float*)d_in[0];
    const float* target       = (const float*)d_in[1];

    cudaFuncSetAttribute(k_fft_yz_reduce,
                         cudaFuncAttributeMaxDynamicSharedMemorySize, SMEM2);

    k_fft_x<<<8 * 128 * 4, 1024>>>(model_output, target);
    k_fft_yz_reduce<<<8 * 65, 1024, SMEM2>>>((float*)d_out);
}